// round 10
// baseline (speedup 1.0000x reference)
#include <cuda_runtime.h>
#include <math.h>
#include <stdint.h>

#define Bz 16
#define C 256
#define H 48
#define W 160
#define HW (H*W)            // 7680
#define CHW (C*HW)          // 1966080

typedef unsigned long long ull;

// Scratch (__device__ globals; no allocations allowed)
__device__ float g_G[(size_t)Bz * 4 * 9 * HW];
__device__ int   g_y0[Bz * HW];
__device__ float g_wy[Bz * HW];
__device__ float g_samp0[Bz * HW];
__device__ float g_Aprep[C * C];   // w_ext[:,1:] tf32, blocked [k/4][m][4k]

// ===================== PTX helpers ==============================
__device__ __forceinline__ void fma2(ull& d, ull a, ull b) {
    asm("fma.rn.f32x2 %0, %1, %2, %0;" : "+l"(d) : "l"(a), "l"(b));
}
__device__ __forceinline__ ull pack2(float lo, float hi) {
    ull r; asm("mov.b64 %0, {%1, %2};" : "=l"(r) : "f"(lo), "f"(hi)); return r;
}
__device__ __forceinline__ float to_tf32(float x) {
    uint32_t u;
    asm("cvt.rna.tf32.f32 %0, %1;" : "=r"(u) : "f"(x));
    return __uint_as_float(u);
}
__device__ __forceinline__ uint32_t smem_u32(const void* p) {
    uint32_t a;
    asm("{ .reg .u64 t; cvta.to.shared.u64 t, %1; cvt.u32.u64 %0, t; }" : "=r"(a) : "l"(p));
    return a;
}
#define CP_ASYNC_4(dst, src) \
    asm volatile("cp.async.ca.shared.global [%0], [%1], 4;" :: "r"(dst), "l"(src))
#define CP_ASYNC_16(dst, src) \
    asm volatile("cp.async.cg.shared.global [%0], [%1], 16;" :: "r"(dst), "l"(src))
#define CP_COMMIT() asm volatile("cp.async.commit_group;" ::: "memory")
#define CP_WAIT(n)  asm volatile("cp.async.wait_group %0;" :: "n"(n) : "memory")

__device__ __forceinline__ void ldsm_x4(uint32_t addr, uint32_t* r) {
    asm volatile("ldmatrix.sync.aligned.m8n8.x4.shared.b16 {%0,%1,%2,%3}, [%4];"
        : "=r"(r[0]), "=r"(r[1]), "=r"(r[2]), "=r"(r[3]) : "r"(addr));
}

__device__ __forceinline__ void mma_tf32(float* d,
                                         uint32_t a0, uint32_t a1, uint32_t a2, uint32_t a3,
                                         float b0, float b1) {
    asm volatile(
        "mma.sync.aligned.m16n8k8.row.col.f32.tf32.tf32.f32 "
        "{%0,%1,%2,%3}, {%4,%5,%6,%7}, {%8,%9}, {%0,%1,%2,%3};"
        : "+f"(d[0]), "+f"(d[1]), "+f"(d[2]), "+f"(d[3])
        : "r"(a0), "r"(a1), "r"(a2), "r"(a3),
          "r"(__float_as_uint(b0)), "r"(__float_as_uint(b1)));
}

// ---------------------------------------------------------------------------
// Kernel 0: w_ext[:,1:] -> g_Aprep blocked [k/4][m][4k], tf32-rounded.
// ---------------------------------------------------------------------------
__global__ void prepA_kernel(const float* __restrict__ w_ext)
{
    const int m = blockIdx.x, k = threadIdx.x;
    g_Aprep[(k >> 2) * (C * 4) + m * 4 + (k & 3)] =
        to_tf32(__ldg(&w_ext[(size_t)m * 257 + 1 + k]));
}

// ---------------------------------------------------------------------------
// Kernel 1: conv phase A, 4 channel-chunks (960 blocks).
// ---------------------------------------------------------------------------
#define CCH 64
__global__ __launch_bounds__(256) void convA_kernel(const float* __restrict__ f,
                                                    const float* __restrict__ w_disp)
{
    __shared__ ull sW2[CCH * 9];
    const int tid   = threadIdx.x;
    const int chunk = blockIdx.y;
    const int b     = blockIdx.z;
    const int p2    = blockIdx.x * 512 + tid * 2;

    for (int i = tid; i < CCH * 9; i += 256) {
        float w = __ldg(&w_disp[chunk * CCH * 9 + i]);
        sW2[i] = pack2(w, w);
    }
    __syncthreads();

    const float* Fb = f + (size_t)b * CHW + (size_t)chunk * CCH * HW;
    ull acc[9];
    #pragma unroll
    for (int j = 0; j < 9; j++) acc[j] = 0ull;

    #pragma unroll 4
    for (int c = 0; c < CCH; c++) {
        ull v = *(const ull*)&Fb[(size_t)c * HW + p2];
        #pragma unroll
        for (int j = 0; j < 9; j++) fma2(acc[j], sW2[c * 9 + j], v);
    }
    #pragma unroll
    for (int j = 0; j < 9; j++)
        *(ull*)&g_G[((size_t)((b * 4 + chunk) * 9 + j)) * HW + p2] = acc[j];
}

// ---------------------------------------------------------------------------
// Kernel 2: 3x3 combine, tanh -> disp, sampling params.
// ---------------------------------------------------------------------------
__global__ __launch_bounds__(256) void phaseB_kernel(const float* __restrict__ P2,
                                                     const float* __restrict__ b_disp)
{
    const int b = blockIdx.y;
    const int p = blockIdx.x * 256 + threadIdx.x;
    const int y = p / W, x = p % W;

    float s = 0.f;
    #pragma unroll
    for (int dy = -1; dy <= 1; dy++) {
        int yy = y + dy;
        if (yy < 0 || yy >= H) continue;
        #pragma unroll
        for (int dx = -1; dx <= 1; dx++) {
            int xx = x + dx;
            if (xx < 0 || xx >= W) continue;
            int j = (dy + 1) * 3 + (dx + 1);
            #pragma unroll
            for (int ch = 0; ch < 4; ch++)
                s += g_G[((size_t)((b * 4 + ch) * 9 + j)) * HW + yy * W + xx];
        }
    }
    const float dval = 0.1f * tanhf(s + __ldg(&b_disp[0]));

    const float fyv = __ldg(&P2[b * 12 + 5]) * 0.0625f;
    const float cyv = __ldg(&P2[b * 12 + 6]) * 0.0625f;
    const float Tyv = __ldg(&P2[b * 12 + 7]) * 0.0625f;
    const float denom = fabsf(fyv * 1.65f + Tyv) + 1e-10f;

    const float yf    = (float)y;
    const float ysb   = fmaxf(1.535f * (yf - cyv) / (2.f * (1.65f - 0.5f * 1.535f)), 0.f) * (1.f / 24.f);
    const float ybase = -1.f + yf * (2.f / 47.f);
    const float gy    = ybase + ysb + dval;

    float iy  = fminf(fmaxf((gy + 1.f) * 0.5f * 47.f, 0.f), 47.f);
    float y0f = floorf(iy);
    float wy  = iy - y0f;
    int y0 = (int)y0f;
    int y1 = min(y0 + 1, H - 1);

    const float sc = fyv * 0.54f / denom;
    float d0 = fmaxf(sc * (y0f - cyv), 0.f);
    float d1 = fmaxf(sc * ((float)y1 - cyv), 0.f);

    const int gi = b * HW + p;
    g_y0[gi]    = y0;
    g_wy[gi]    = wy;
    g_samp0[gi] = d0 + wy * (d1 - d0);
}

// ---------------------------------------------------------------------------
// Kernel 3: tf32 mma.sync GEMM. 256(o) x 128(px) per CTA, K chunks of 32.
// 3-buffer cp.async pipeline, ONE sync/chunk, prefetch AFTER compute.
// Quad-vectorized tap gather: pixels in an x%4 quad with uniform y0/y1 load
// via one cp.async.16 instead of four cp.async.4.
// ---------------------------------------------------------------------------
#define GM 256
#define GN 128
#define GK 32
#define NCH (C / GK)                    // 8
#define BSTR 132
#define ABUF  (GM * GK * 4)             // 32768 B
#define BBUF  (GK * BSTR * 4)           // 16896 B
#define OFF_A   0
#define OFF_V0  (3 * ABUF)              // 98304
#define OFF_V1  (OFF_V0 + 3 * BBUF)     // 148992
#define OFF_CTL (OFF_V1 + 3 * BBUF)     // 199680
#define SMEM_TOT (OFF_CTL + 2304)

__global__ __launch_bounds__(512, 1) void gemm_mma_kernel(
    const float* __restrict__ f,
    const float* __restrict__ w_ext,
    const float* __restrict__ b_ext,
    const float* __restrict__ alpha,
    float* __restrict__ out)
{
    extern __shared__ __align__(16) char smem[];
    const uint32_t sb = smem_u32(smem);

    int*   sO0 = (int*)  (smem + OFF_CTL);          // 128 ints
    int*   sO1 = (int*)  (smem + OFF_CTL + 512);
    float* sWy = (float*)(smem + OFF_CTL + 1024);
    float* sSm = (float*)(smem + OFF_CTL + 1536);
    int*   sQ  = (int*)  (smem + OFF_CTL + 2048);   // 32 quad flags

    const int tid  = threadIdx.x;
    const int warp = tid >> 5;
    const int lane = tid & 31;
    const int lg   = lane >> 2;
    const int lt   = lane & 3;
    const int wm   = (warp >> 2) * 64;
    const int wn   = (warp & 3) * 32;

    const int b  = blockIdx.z;
    const int n0 = blockIdx.x * GN;
    const float* Fb = f + (size_t)b * CHW;

    if (tid < GN) {
        int p   = n0 + tid;
        int y0v = g_y0[b * HW + p];
        int x   = p % W;
        sO0[tid] = y0v * W + x;
        sO1[tid] = min(y0v + 1, H - 1) * W + x;
        sWy[tid] = g_wy[b * HW + p];
        sSm[tid] = g_samp0[b * HW + p];
    }
    __syncthreads();
    if (tid < 32) {   // quad uniformity flags
        int base = tid * 4;
        int ok = 1;
        #pragma unroll
        for (int j = 1; j < 4; j++) {
            ok &= (sO0[base + j] == sO0[base] + j);
            ok &= (sO1[base + j] == sO1[base] + j);
        }
        sQ[tid] = ok;
    }
    __syncthreads();

    // ---- async prefetch of one K-chunk into buffer `buf` ----
    auto prefetch = [&](int c, int buf) {
        const uint32_t ab  = sb + OFF_A  + buf * ABUF;
        const uint32_t v0b = sb + OFF_V0 + buf * BBUF;
        const uint32_t v1b = sb + OFF_V1 + buf * BBUF;
        #pragma unroll
        for (int i = 0; i < 4; i++) {
            int e = tid + i * 512;            // 2048 16B units of A
            const float* src = g_Aprep + (size_t)(c * 8 + (e >> 8)) * (C * 4) + (e & 255) * 4;
            CP_ASYNC_16(ab + e * 16, src);
        }
        // B taps: 2 taps x 32 k x 32 quads = 2048 quad-ops, 4 per thread
        #pragma unroll
        for (int i = 0; i < 4; i++) {
            int e   = tid + i * 512;
            int tap = e >> 10;                // 0: v0, 1: v1
            int r   = e & 1023;
            int k   = r >> 5;
            int nq  = r & 31;
            const float* fk = Fb + (size_t)(c * GK + k) * HW;
            const int* sOf  = tap ? sO1 : sO0;
            uint32_t dst = (tap ? v1b : v0b) + (uint32_t)(k * BSTR + nq * 4) * 4;
            int base = nq * 4;
            if (sQ[nq]) {
                CP_ASYNC_16(dst, fk + sOf[base]);
            } else {
                #pragma unroll
                for (int j = 0; j < 4; j++)
                    CP_ASYNC_4(dst + j * 4, fk + sOf[base + j]);
            }
        }
        CP_COMMIT();
    };

    float acc[4][4][4];
    #pragma unroll
    for (int mi = 0; mi < 4; mi++)
        #pragma unroll
        for (int nj = 0; nj < 4; nj++)
            #pragma unroll
            for (int t = 0; t < 4; t++) acc[mi][nj][t] = 0.f;

    float wv[4];
    #pragma unroll
    for (int nj = 0; nj < 4; nj++) wv[nj] = sWy[wn + nj * 8 + lg];

    const uint32_t laneoff = (uint32_t)(((lane >> 4) * GM + (lane & 15)) * 16);

    prefetch(0, 0);
    prefetch(1, 1);

    for (int c = 0; c < NCH; c++) {
        const int buf = c % 3;
        if (c < NCH - 1) CP_WAIT(1); else CP_WAIT(0);
        __syncthreads();

        const uint32_t abase = sb + OFF_A + buf * ABUF;
        const float* V0 = (const float*)(smem + OFF_V0 + buf * BBUF);
        const float* V1 = (const float*)(smem + OFF_V1 + buf * BBUF);

        #pragma unroll
        for (int ks = 0; ks < 4; ks++) {
            const int kb = ks * 8;
            uint32_t af[4][4];
            #pragma unroll
            for (int mi = 0; mi < 4; mi++) {
                uint32_t addr = abase + (uint32_t)((ks * 2 * GM + wm + mi * 16) * 16) + laneoff;
                ldsm_x4(addr, af[mi]);
            }
            float bf[4][2];
            #pragma unroll
            for (int nj = 0; nj < 4; nj++) {
                int n   = wn + nj * 8 + lg;
                int i0  = (kb + lt) * BSTR + n;
                int i1  = (kb + lt + 4) * BSTR + n;
                float a0 = V0[i0], b0v = V1[i0];
                float a1 = V0[i1], b1v = V1[i1];
                bf[nj][0] = to_tf32(fmaf(wv[nj], b0v - a0, a0));
                bf[nj][1] = to_tf32(fmaf(wv[nj], b1v - a1, a1));
            }
            #pragma unroll
            for (int mi = 0; mi < 4; mi++)
                #pragma unroll
                for (int nj = 0; nj < 4; nj++)
                    mma_tf32(acc[mi][nj],
                             af[mi][0], af[mi][1], af[mi][2], af[mi][3],
                             bf[nj][0], bf[nj][1]);
        }
        if (c + 2 < NCH) prefetch(c + 2, (c + 2) % 3);   // AFTER compute
    }

    // ---- fused epilogue ----
    const float al = __ldg(&alpha[0]);
    #pragma unroll
    for (int mi = 0; mi < 4; mi++) {
        const int r0 = wm + mi * 16 + lg;
        const float w0a = __ldg(&w_ext[(size_t)r0 * 257]);
        const float bea = __ldg(&b_ext[r0]);
        const float w0b = __ldg(&w_ext[(size_t)(r0 + 8) * 257]);
        const float beb = __ldg(&b_ext[r0 + 8]);
        #pragma unroll
        for (int nj = 0; nj < 4; nj++) {
            const int cl  = wn + nj * 8 + 2 * lt;
            const int col = n0 + cl;
            const float s0 = sSm[cl], s1 = sSm[cl + 1];

            size_t oa = ((size_t)b * C + r0) * HW + col;
            size_t ob = oa + (size_t)8 * HW;

            float2 fa = *(const float2*)(f + oa);
            float2 fb = *(const float2*)(f + ob);
            float2 ra, rb;
            ra.x = fmaxf(fa.x + al * (acc[mi][nj][0] + w0a * s0 + bea), 0.f);
            ra.y = fmaxf(fa.y + al * (acc[mi][nj][1] + w0a * s1 + bea), 0.f);
            rb.x = fmaxf(fb.x + al * (acc[mi][nj][2] + w0b * s0 + beb), 0.f);
            rb.y = fmaxf(fb.y + al * (acc[mi][nj][3] + w0b * s1 + beb), 0.f);
            *(float2*)(out + oa) = ra;
            *(float2*)(out + ob) = rb;
        }
    }
}

// ---------------------------------------------------------------------------
extern "C" void kernel_launch(void* const* d_in, const int* in_sizes, int n_in,
                              void* d_out, int out_size)
{
    const float* features = (const float*)d_in[0];
    const float* P2       = (const float*)d_in[1];
    const float* w_disp   = (const float*)d_in[2];
    const float* b_disp   = (const float*)d_in[3];
    const float* w_ext    = (const float*)d_in[4];
    const float* b_ext    = (const float*)d_in[5];
    const float* alpha    = (const float*)d_in[6];
    float* out = (float*)d_out;

    cudaFuncSetAttribute(gemm_mma_kernel,
                         cudaFuncAttributeMaxDynamicSharedMemorySize, SMEM_TOT);

    prepA_kernel <<<C, C>>>(w_ext);
    convA_kernel <<<dim3(HW / 512, 4, Bz), 256>>>(features, w_disp);
    phaseB_kernel<<<dim3(HW / 256, Bz), 256>>>(P2, b_disp);
    gemm_mma_kernel<<<dim3(HW / GN, 1, Bz), 512, SMEM_TOT>>>(
        features, w_ext, b_ext, alpha, out);
}

// round 12
// speedup vs baseline: 1.3940x; 1.3940x over previous
#include <cuda_runtime.h>
#include <math.h>
#include <stdint.h>

#define Bz 16
#define C 256
#define H 48
#define W 160
#define HW (H*W)            // 7680
#define CHW (C*HW)          // 1966080

typedef unsigned long long ull;

// Scratch (__device__ globals; no allocations allowed)
__device__ float g_G[(size_t)Bz * 4 * 9 * HW];
__device__ int   g_y0[Bz * HW];
__device__ float g_wy[Bz * HW];
__device__ float g_samp0[Bz * HW];
__device__ float g_Aprep[C * C];   // w_ext[:,1:] tf32, blocked [k/4][m][4k]

// ===================== PTX helpers ==============================
__device__ __forceinline__ void fma2(ull& d, ull a, ull b) {
    asm("fma.rn.f32x2 %0, %1, %2, %0;" : "+l"(d) : "l"(a), "l"(b));
}
__device__ __forceinline__ ull pack2(float lo, float hi) {
    ull r; asm("mov.b64 %0, {%1, %2};" : "=l"(r) : "f"(lo), "f"(hi)); return r;
}
__device__ __forceinline__ float to_tf32(float x) {
    uint32_t u;
    asm("cvt.rna.tf32.f32 %0, %1;" : "=r"(u) : "f"(x));
    return __uint_as_float(u);
}
__device__ __forceinline__ uint32_t smem_u32(const void* p) {
    uint32_t a;
    asm("{ .reg .u64 t; cvta.to.shared.u64 t, %1; cvt.u32.u64 %0, t; }" : "=r"(a) : "l"(p));
    return a;
}
#define CP_ASYNC_4(dst, src) \
    asm volatile("cp.async.ca.shared.global [%0], [%1], 4;" :: "r"(dst), "l"(src))
#define CP_ASYNC_16(dst, src) \
    asm volatile("cp.async.cg.shared.global [%0], [%1], 16;" :: "r"(dst), "l"(src))
#define CP_COMMIT() asm volatile("cp.async.commit_group;" ::: "memory")
#define CP_WAIT(n)  asm volatile("cp.async.wait_group %0;" :: "n"(n) : "memory")

__device__ __forceinline__ void ldsm_x4(uint32_t addr, uint32_t* r) {
    asm volatile("ldmatrix.sync.aligned.m8n8.x4.shared.b16 {%0,%1,%2,%3}, [%4];"
        : "=r"(r[0]), "=r"(r[1]), "=r"(r[2]), "=r"(r[3]) : "r"(addr));
}

__device__ __forceinline__ void mma_tf32(float* d,
                                         uint32_t a0, uint32_t a1, uint32_t a2, uint32_t a3,
                                         float b0, float b1) {
    asm volatile(
        "mma.sync.aligned.m16n8k8.row.col.f32.tf32.tf32.f32 "
        "{%0,%1,%2,%3}, {%4,%5,%6,%7}, {%8,%9}, {%0,%1,%2,%3};"
        : "+f"(d[0]), "+f"(d[1]), "+f"(d[2]), "+f"(d[3])
        : "r"(a0), "r"(a1), "r"(a2), "r"(a3),
          "r"(__float_as_uint(b0)), "r"(__float_as_uint(b1)));
}

// ---------------------------------------------------------------------------
// Kernel 0: w_ext[:,1:] -> g_Aprep blocked [k/4][m][4k], tf32-rounded.
// ---------------------------------------------------------------------------
__global__ void prepA_kernel(const float* __restrict__ w_ext)
{
    const int m = blockIdx.x, k = threadIdx.x;
    g_Aprep[(k >> 2) * (C * 4) + m * 4 + (k & 3)] =
        to_tf32(__ldg(&w_ext[(size_t)m * 257 + 1 + k]));
}

// ---------------------------------------------------------------------------
// Kernel 1: conv phase A, 4 channel-chunks (960 blocks).
// ---------------------------------------------------------------------------
#define CCH 64
__global__ __launch_bounds__(256) void convA_kernel(const float* __restrict__ f,
                                                    const float* __restrict__ w_disp)
{
    __shared__ ull sW2[CCH * 9];
    const int tid   = threadIdx.x;
    const int chunk = blockIdx.y;
    const int b     = blockIdx.z;
    const int p2    = blockIdx.x * 512 + tid * 2;

    for (int i = tid; i < CCH * 9; i += 256) {
        float w = __ldg(&w_disp[chunk * CCH * 9 + i]);
        sW2[i] = pack2(w, w);
    }
    __syncthreads();

    const float* Fb = f + (size_t)b * CHW + (size_t)chunk * CCH * HW;
    ull acc[9];
    #pragma unroll
    for (int j = 0; j < 9; j++) acc[j] = 0ull;

    #pragma unroll 4
    for (int c = 0; c < CCH; c++) {
        ull v = *(const ull*)&Fb[(size_t)c * HW + p2];
        #pragma unroll
        for (int j = 0; j < 9; j++) fma2(acc[j], sW2[c * 9 + j], v);
    }
    #pragma unroll
    for (int j = 0; j < 9; j++)
        *(ull*)&g_G[((size_t)((b * 4 + chunk) * 9 + j)) * HW + p2] = acc[j];
}

// ---------------------------------------------------------------------------
// Kernel 2: 3x3 combine, tanh -> disp, sampling params.
// ---------------------------------------------------------------------------
__global__ __launch_bounds__(256) void phaseB_kernel(const float* __restrict__ P2,
                                                     const float* __restrict__ b_disp)
{
    const int b = blockIdx.y;
    const int p = blockIdx.x * 256 + threadIdx.x;
    const int y = p / W, x = p % W;

    float s = 0.f;
    #pragma unroll
    for (int dy = -1; dy <= 1; dy++) {
        int yy = y + dy;
        if (yy < 0 || yy >= H) continue;
        #pragma unroll
        for (int dx = -1; dx <= 1; dx++) {
            int xx = x + dx;
            if (xx < 0 || xx >= W) continue;
            int j = (dy + 1) * 3 + (dx + 1);
            #pragma unroll
            for (int ch = 0; ch < 4; ch++)
                s += g_G[((size_t)((b * 4 + ch) * 9 + j)) * HW + yy * W + xx];
        }
    }
    const float dval = 0.1f * tanhf(s + __ldg(&b_disp[0]));

    const float fyv = __ldg(&P2[b * 12 + 5]) * 0.0625f;
    const float cyv = __ldg(&P2[b * 12 + 6]) * 0.0625f;
    const float Tyv = __ldg(&P2[b * 12 + 7]) * 0.0625f;
    const float denom = fabsf(fyv * 1.65f + Tyv) + 1e-10f;

    const float yf    = (float)y;
    const float ysb   = fmaxf(1.535f * (yf - cyv) / (2.f * (1.65f - 0.5f * 1.535f)), 0.f) * (1.f / 24.f);
    const float ybase = -1.f + yf * (2.f / 47.f);
    const float gy    = ybase + ysb + dval;

    float iy  = fminf(fmaxf((gy + 1.f) * 0.5f * 47.f, 0.f), 47.f);
    float y0f = floorf(iy);
    float wy  = iy - y0f;
    int y0 = (int)y0f;
    int y1 = min(y0 + 1, H - 1);

    const float sc = fyv * 0.54f / denom;
    float d0 = fmaxf(sc * (y0f - cyv), 0.f);
    float d1 = fmaxf(sc * ((float)y1 - cyv), 0.f);

    const int gi = b * HW + p;
    g_y0[gi]    = y0;
    g_wy[gi]    = wy;
    g_samp0[gi] = d0 + wy * (d1 - d0);
}

// ---------------------------------------------------------------------------
// Kernel 3: tf32 mma.sync GEMM — R8 pipeline (2 buffers, wait+sync, compute,
// sync, prefetch-after), single change: A fragments via ldmatrix.x4 from the
// blocked [kq][m][16B] layout.
// ---------------------------------------------------------------------------
#define GM 256
#define GN 128
#define GK 32
#define NCH (C / GK)                    // 8
#define BSTR 132
#define ABUF  (GM * GK * 4)             // 32768 B (blocked, no padding)
#define BBUF  (GK * BSTR * 4)           // 16896 B
#define OFF_A   0
#define OFF_V0  (2 * ABUF)              // 65536
#define OFF_V1  (OFF_V0 + 2 * BBUF)     // 99328
#define OFF_CTL (OFF_V1 + 2 * BBUF)     // 133120
#define SMEM_TOT (OFF_CTL + 2048)       // 135168

__global__ __launch_bounds__(512, 1) void gemm_mma_kernel(
    const float* __restrict__ f,
    const float* __restrict__ w_ext,
    const float* __restrict__ b_ext,
    const float* __restrict__ alpha,
    float* __restrict__ out)
{
    extern __shared__ __align__(16) char smem[];
    const uint32_t sb = smem_u32(smem);

    int*   sO0 = (int*)  (smem + OFF_CTL);
    int*   sO1 = (int*)  (smem + OFF_CTL + 512);
    float* sWy = (float*)(smem + OFF_CTL + 1024);
    float* sSm = (float*)(smem + OFF_CTL + 1536);

    const int tid  = threadIdx.x;
    const int warp = tid >> 5;
    const int lane = tid & 31;
    const int lg   = lane >> 2;
    const int lt   = lane & 3;
    const int wm   = (warp >> 2) * 64;
    const int wn   = (warp & 3) * 32;

    const int b  = blockIdx.z;
    const int n0 = blockIdx.x * GN;
    const float* Fb = f + (size_t)b * CHW;

    if (tid < GN) {
        int p   = n0 + tid;
        int y0v = g_y0[b * HW + p];
        int x   = p % W;
        sO0[tid] = y0v * W + x;
        sO1[tid] = min(y0v + 1, H - 1) * W + x;
        sWy[tid] = g_wy[b * HW + p];
        sSm[tid] = g_samp0[b * HW + p];
    }
    __syncthreads();

    // ---- async prefetch of one K-chunk into buffer `buf` ----
    auto prefetch = [&](int c, int buf) {
        const uint32_t ab  = sb + OFF_A  + buf * ABUF;
        const uint32_t v0b = sb + OFF_V0 + buf * BBUF;
        const uint32_t v1b = sb + OFF_V1 + buf * BBUF;
        #pragma unroll
        for (int i = 0; i < 4; i++) {
            int e = tid + i * 512;            // 2048 16B units of A (blocked)
            const float* src = g_Aprep + (size_t)(c * 8 + (e >> 8)) * (C * 4) + (e & 255) * 4;
            CP_ASYNC_16(ab + e * 16, src);
        }
        #pragma unroll
        for (int i = 0; i < 8; i++) {
            int e = tid + i * 512;            // 4096 B positions
            int k = e >> 7;
            int n = e & 127;
            const float* fk = Fb + (size_t)(c * GK + k) * HW;
            uint32_t doff = (k * BSTR + n) * 4;
            CP_ASYNC_4(v0b + doff, fk + sO0[n]);
            CP_ASYNC_4(v1b + doff, fk + sO1[n]);
        }
        CP_COMMIT();
    };

    float acc[4][4][4];
    #pragma unroll
    for (int mi = 0; mi < 4; mi++)
        #pragma unroll
        for (int nj = 0; nj < 4; nj++)
            #pragma unroll
            for (int t = 0; t < 4; t++) acc[mi][nj][t] = 0.f;

    float wv[4];
    #pragma unroll
    for (int nj = 0; nj < 4; nj++) wv[nj] = sWy[wn + nj * 8 + lg];

    // per-lane ldmatrix row-offset: lanes 0-15 -> kq even block rows,
    // lanes 16-31 -> kq odd block rows
    const uint32_t laneoff = (uint32_t)(((lane >> 4) * GM + (lane & 15)) * 16);

    prefetch(0, 0);
    prefetch(1, 1);

    for (int c = 0; c < NCH; c++) {
        const int buf = c & 1;
        if (c < NCH - 1) CP_WAIT(1); else CP_WAIT(0);
        __syncthreads();

        const uint32_t abase = sb + OFF_A + buf * ABUF;
        const float* V0 = (const float*)(smem + OFF_V0 + buf * BBUF);
        const float* V1 = (const float*)(smem + OFF_V1 + buf * BBUF);

        #pragma unroll
        for (int ks = 0; ks < 4; ks++) {
            const int kb = ks * 8;
            uint32_t af[4][4];
            #pragma unroll
            for (int mi = 0; mi < 4; mi++) {
                uint32_t addr = abase + (uint32_t)((ks * 2 * GM + wm + mi * 16) * 16) + laneoff;
                ldsm_x4(addr, af[mi]);
            }
            float bf[4][2];
            #pragma unroll
            for (int nj = 0; nj < 4; nj++) {
                int n   = wn + nj * 8 + lg;
                int i0  = (kb + lt) * BSTR + n;
                int i1  = (kb + lt + 4) * BSTR + n;
                float a0 = V0[i0], b0v = V1[i0];
                float a1 = V0[i1], b1v = V1[i1];
                bf[nj][0] = to_tf32(fmaf(wv[nj], b0v - a0, a0));
                bf[nj][1] = to_tf32(fmaf(wv[nj], b1v - a1, a1));
            }
            #pragma unroll
            for (int mi = 0; mi < 4; mi++)
                #pragma unroll
                for (int nj = 0; nj < 4; nj++)
                    mma_tf32(acc[mi][nj],
                             af[mi][0], af[mi][1], af[mi][2], af[mi][3],
                             bf[nj][0], bf[nj][1]);
        }
        __syncthreads();
        if (c + 2 < NCH) prefetch(c + 2, buf);
    }

    // ---- fused epilogue ----
    const float al = __ldg(&alpha[0]);
    #pragma unroll
    for (int mi = 0; mi < 4; mi++) {
        const int r0 = wm + mi * 16 + lg;
        const float w0a = __ldg(&w_ext[(size_t)r0 * 257]);
        const float bea = __ldg(&b_ext[r0]);
        const float w0b = __ldg(&w_ext[(size_t)(r0 + 8) * 257]);
        const float beb = __ldg(&b_ext[r0 + 8]);
        #pragma unroll
        for (int nj = 0; nj < 4; nj++) {
            const int cl  = wn + nj * 8 + 2 * lt;
            const int col = n0 + cl;
            const float s0 = sSm[cl], s1 = sSm[cl + 1];

            size_t oa = ((size_t)b * C + r0) * HW + col;
            size_t ob = oa + (size_t)8 * HW;

            float2 fa = *(const float2*)(f + oa);
            float2 fb = *(const float2*)(f + ob);
            float2 ra, rb;
            ra.x = fmaxf(fa.x + al * (acc[mi][nj][0] + w0a * s0 + bea), 0.f);
            ra.y = fmaxf(fa.y + al * (acc[mi][nj][1] + w0a * s1 + bea), 0.f);
            rb.x = fmaxf(fb.x + al * (acc[mi][nj][2] + w0b * s0 + beb), 0.f);
            rb.y = fmaxf(fb.y + al * (acc[mi][nj][3] + w0b * s1 + beb), 0.f);
            *(float2*)(out + oa) = ra;
            *(float2*)(out + ob) = rb;
        }
    }
}

// ---------------------------------------------------------------------------
extern "C" void kernel_launch(void* const* d_in, const int* in_sizes, int n_in,
                              void* d_out, int out_size)
{
    const float* features = (const float*)d_in[0];
    const float* P2       = (const float*)d_in[1];
    const float* w_disp   = (const float*)d_in[2];
    const float* b_disp   = (const float*)d_in[3];
    const float* w_ext    = (const float*)d_in[4];
    const float* b_ext    = (const float*)d_in[5];
    const float* alpha    = (const float*)d_in[6];
    float* out = (float*)d_out;

    cudaFuncSetAttribute(gemm_mma_kernel,
                         cudaFuncAttributeMaxDynamicSharedMemorySize, SMEM_TOT);

    prepA_kernel <<<C, C>>>(w_ext);
    convA_kernel <<<dim3(HW / 512, 4, Bz), 256>>>(features, w_disp);
    phaseB_kernel<<<dim3(HW / 256, Bz), 256>>>(P2, b_disp);
    gemm_mma_kernel<<<dim3(HW / GN, 1, Bz), 512, SMEM_TOT>>>(
        features, w_ext, b_ext, alpha, out);
}

// round 13
// speedup vs baseline: 1.7915x; 1.2851x over previous
#include <cuda_runtime.h>
#include <cuda_fp16.h>
#include <math.h>
#include <stdint.h>

#define Bz 16
#define C 256
#define H 48
#define W 160
#define HW (H*W)            // 7680
#define CHW (C*HW)          // 1966080

typedef unsigned long long ull;

// Scratch (__device__ globals; no allocations allowed)
__device__ float  g_G[(size_t)Bz * 4 * 9 * HW];
__device__ int    g_y0[Bz * HW];
__device__ float  g_wy[Bz * HW];
__device__ float  g_samp0[Bz * HW];
__device__ __half g_Ah[C * C];   // w_ext[:,1:] f16, blocked [k/8][m][8k]

// ===================== PTX helpers ==============================
__device__ __forceinline__ void fma2(ull& d, ull a, ull b) {
    asm("fma.rn.f32x2 %0, %1, %2, %0;" : "+l"(d) : "l"(a), "l"(b));
}
__device__ __forceinline__ ull pack2(float lo, float hi) {
    ull r; asm("mov.b64 %0, {%1, %2};" : "=l"(r) : "f"(lo), "f"(hi)); return r;
}
__device__ __forceinline__ uint32_t smem_u32(const void* p) {
    uint32_t a;
    asm("{ .reg .u64 t; cvta.to.shared.u64 t, %1; cvt.u32.u64 %0, t; }" : "=r"(a) : "l"(p));
    return a;
}
#define CP_ASYNC_4(dst, src) \
    asm volatile("cp.async.ca.shared.global [%0], [%1], 4;" :: "r"(dst), "l"(src))
#define CP_ASYNC_16(dst, src) \
    asm volatile("cp.async.cg.shared.global [%0], [%1], 16;" :: "r"(dst), "l"(src))
#define CP_COMMIT() asm volatile("cp.async.commit_group;" ::: "memory")
#define CP_WAIT(n)  asm volatile("cp.async.wait_group %0;" :: "n"(n) : "memory")

__device__ __forceinline__ void ldsm_x4(uint32_t addr, uint32_t* r) {
    asm volatile("ldmatrix.sync.aligned.m8n8.x4.shared.b16 {%0,%1,%2,%3}, [%4];"
        : "=r"(r[0]), "=r"(r[1]), "=r"(r[2]), "=r"(r[3]) : "r"(addr));
}
__device__ __forceinline__ void ldsm_x2_trans(uint32_t addr, uint32_t* r) {
    asm volatile("ldmatrix.sync.aligned.m8n8.x2.trans.shared.b16 {%0,%1}, [%2];"
        : "=r"(r[0]), "=r"(r[1]) : "r"(addr));
}

// m16n8k16 f16 MMA, f32 accumulate
__device__ __forceinline__ void mma_f16(float* d,
                                        uint32_t a0, uint32_t a1, uint32_t a2, uint32_t a3,
                                        uint32_t b0, uint32_t b1) {
    asm volatile(
        "mma.sync.aligned.m16n8k16.row.col.f32.f16.f16.f32 "
        "{%0,%1,%2,%3}, {%4,%5,%6,%7}, {%8,%9}, {%0,%1,%2,%3};"
        : "+f"(d[0]), "+f"(d[1]), "+f"(d[2]), "+f"(d[3])
        : "r"(a0), "r"(a1), "r"(a2), "r"(a3), "r"(b0), "r"(b1));
}

// ---------------------------------------------------------------------------
// Kernel 0: w_ext[:,1:] -> g_Ah blocked [k/8][m][8k], f16.
// ---------------------------------------------------------------------------
__global__ void prepA_kernel(const float* __restrict__ w_ext)
{
    const int m = blockIdx.x, k = threadIdx.x;
    g_Ah[(k >> 3) * (C * 8) + m * 8 + (k & 7)] =
        __float2half(__ldg(&w_ext[(size_t)m * 257 + 1 + k]));
}

// ---------------------------------------------------------------------------
// Kernel 1: conv phase A, 4 channel-chunks (960 blocks).
// ---------------------------------------------------------------------------
#define CCH 64
__global__ __launch_bounds__(256) void convA_kernel(const float* __restrict__ f,
                                                    const float* __restrict__ w_disp)
{
    __shared__ ull sW2[CCH * 9];
    const int tid   = threadIdx.x;
    const int chunk = blockIdx.y;
    const int b     = blockIdx.z;
    const int p2    = blockIdx.x * 512 + tid * 2;

    for (int i = tid; i < CCH * 9; i += 256) {
        float w = __ldg(&w_disp[chunk * CCH * 9 + i]);
        sW2[i] = pack2(w, w);
    }
    __syncthreads();

    const float* Fb = f + (size_t)b * CHW + (size_t)chunk * CCH * HW;
    ull acc[9];
    #pragma unroll
    for (int j = 0; j < 9; j++) acc[j] = 0ull;

    #pragma unroll 4
    for (int c = 0; c < CCH; c++) {
        ull v = *(const ull*)&Fb[(size_t)c * HW + p2];
        #pragma unroll
        for (int j = 0; j < 9; j++) fma2(acc[j], sW2[c * 9 + j], v);
    }
    #pragma unroll
    for (int j = 0; j < 9; j++)
        *(ull*)&g_G[((size_t)((b * 4 + chunk) * 9 + j)) * HW + p2] = acc[j];
}

// ---------------------------------------------------------------------------
// Kernel 2: 3x3 combine, tanh -> disp, sampling params.
// ---------------------------------------------------------------------------
__global__ __launch_bounds__(256) void phaseB_kernel(const float* __restrict__ P2,
                                                     const float* __restrict__ b_disp)
{
    const int b = blockIdx.y;
    const int p = blockIdx.x * 256 + threadIdx.x;
    const int y = p / W, x = p % W;

    float s = 0.f;
    #pragma unroll
    for (int dy = -1; dy <= 1; dy++) {
        int yy = y + dy;
        if (yy < 0 || yy >= H) continue;
        #pragma unroll
        for (int dx = -1; dx <= 1; dx++) {
            int xx = x + dx;
            if (xx < 0 || xx >= W) continue;
            int j = (dy + 1) * 3 + (dx + 1);
            #pragma unroll
            for (int ch = 0; ch < 4; ch++)
                s += g_G[((size_t)((b * 4 + ch) * 9 + j)) * HW + yy * W + xx];
        }
    }
    const float dval = 0.1f * tanhf(s + __ldg(&b_disp[0]));

    const float fyv = __ldg(&P2[b * 12 + 5]) * 0.0625f;
    const float cyv = __ldg(&P2[b * 12 + 6]) * 0.0625f;
    const float Tyv = __ldg(&P2[b * 12 + 7]) * 0.0625f;
    const float denom = fabsf(fyv * 1.65f + Tyv) + 1e-10f;

    const float yf    = (float)y;
    const float ysb   = fmaxf(1.535f * (yf - cyv) / (2.f * (1.65f - 0.5f * 1.535f)), 0.f) * (1.f / 24.f);
    const float ybase = -1.f + yf * (2.f / 47.f);
    const float gy    = ybase + ysb + dval;

    float iy  = fminf(fmaxf((gy + 1.f) * 0.5f * 47.f, 0.f), 47.f);
    float y0f = floorf(iy);
    float wy  = iy - y0f;
    int y0 = (int)y0f;
    int y1 = min(y0 + 1, H - 1);

    const float sc = fyv * 0.54f / denom;
    float d0 = fmaxf(sc * (y0f - cyv), 0.f);
    float d1 = fmaxf(sc * ((float)y1 - cyv), 0.f);

    const int gi = b * HW + p;
    g_y0[gi]    = y0;
    g_wy[gi]    = wy;
    g_samp0[gi] = d0 + wy * (d1 - d0);
}

// ---------------------------------------------------------------------------
// Kernel 3: f16 m16n8k16 mma.sync GEMM.
// 256(o) x 128(px) per CTA, K chunks of 32. cp.async taps (fp32, 2-slot) ->
// staged lerp+cvt into f16 Bh tile (1 slot) -> ldmatrix.x2.trans B fragments.
// A f16 blocked, 3-slot rotation, ldmatrix.x4. 2 syncs/chunk.
// ---------------------------------------------------------------------------
#define GM 256
#define GN 128
#define GK 32
#define NCH (C / GK)                    // 8
#define BSTR 132
#define BHSTR 272                       // bytes per k-row of Bh (f16)
#define ABUF  (GM * GK * 2)             // 16384 B (f16 blocked)
#define VBUF  (GK * BSTR * 4)           // 16896 B
#define OFF_A   0
#define OFF_V0  (3 * ABUF)              // 49152
#define OFF_V1  (OFF_V0 + 2 * VBUF)     // 82944
#define OFF_BH  (OFF_V1 + 2 * VBUF)     // 116736
#define OFF_CTL (OFF_BH + GK * BHSTR)   // 125440
#define SMEM_TOT (OFF_CTL + 2048)       // 127488

__global__ __launch_bounds__(512, 1) void gemm_mma_kernel(
    const float* __restrict__ f,
    const float* __restrict__ w_ext,
    const float* __restrict__ b_ext,
    const float* __restrict__ alpha,
    float* __restrict__ out)
{
    extern __shared__ __align__(16) char smem[];
    const uint32_t sb = smem_u32(smem);

    int*   sO0 = (int*)  (smem + OFF_CTL);
    int*   sO1 = (int*)  (smem + OFF_CTL + 512);
    float* sWy = (float*)(smem + OFF_CTL + 1024);
    float* sSm = (float*)(smem + OFF_CTL + 1536);

    const int tid  = threadIdx.x;
    const int warp = tid >> 5;
    const int lane = tid & 31;
    const int lg   = lane >> 2;
    const int lt   = lane & 3;
    const int wm   = (warp >> 2) * 64;
    const int wn   = (warp & 3) * 32;

    const int b  = blockIdx.z;
    const int n0 = blockIdx.x * GN;
    const float* Fb = f + (size_t)b * CHW;

    if (tid < GN) {
        int p   = n0 + tid;
        int y0v = g_y0[b * HW + p];
        int x   = p % W;
        sO0[tid] = y0v * W + x;
        sO1[tid] = min(y0v + 1, H - 1) * W + x;
        sWy[tid] = g_wy[b * HW + p];
        sSm[tid] = g_samp0[b * HW + p];
    }
    __syncthreads();

    // ---- async prefetch: A -> slot c%3, taps -> slot c&1 ----
    auto prefetch = [&](int c) {
        const uint32_t ab  = sb + OFF_A  + (c % 3) * ABUF;
        const uint32_t v0b = sb + OFF_V0 + (c & 1) * VBUF;
        const uint32_t v1b = sb + OFF_V1 + (c & 1) * VBUF;
        #pragma unroll
        for (int i = 0; i < 2; i++) {
            int e = tid + i * 512;            // 1024 16B units of A (f16 blocked)
            const __half* src = g_Ah + (size_t)(c * 4 + (e >> 8)) * (C * 8) + (e & 255) * 8;
            CP_ASYNC_16(ab + e * 16, src);
        }
        #pragma unroll
        for (int i = 0; i < 8; i++) {
            int e = tid + i * 512;            // 4096 tap positions
            int k = e >> 7;
            int n = e & 127;
            const float* fk = Fb + (size_t)(c * GK + k) * HW;
            uint32_t doff = (k * BSTR + n) * 4;
            CP_ASYNC_4(v0b + doff, fk + sO0[n]);
            CP_ASYNC_4(v1b + doff, fk + sO1[n]);
        }
        CP_COMMIT();
    };

    float acc[4][4][4];
    #pragma unroll
    for (int mi = 0; mi < 4; mi++)
        #pragma unroll
        for (int nj = 0; nj < 4; nj++)
            #pragma unroll
            for (int t = 0; t < 4; t++) acc[mi][nj][t] = 0.f;

    const uint32_t laneoff = (uint32_t)(((lane >> 4) * GM + (lane & 15)) * 16);
    const uint32_t bh = sb + OFF_BH;

    prefetch(0);
    prefetch(1);

    for (int c = 0; c < NCH; c++) {
        if (c < NCH - 1) CP_WAIT(1); else CP_WAIT(0);
        __syncthreads();

        // ---- stage: lerp fp32 taps -> f16 Bh[k][n] ----
        {
            const float* V0 = (const float*)(smem + OFF_V0 + (c & 1) * VBUF);
            const float* V1 = (const float*)(smem + OFF_V1 + (c & 1) * VBUF);
            #pragma unroll
            for (int i = 0; i < 4; i++) {
                int e2 = tid + i * 512;       // 2048 half2 positions
                int k  = e2 >> 6;
                int n2 = e2 & 63;
                int idx = k * BSTR + 2 * n2;
                float2 a = *(const float2*)(V0 + idx);
                float2 bv = *(const float2*)(V1 + idx);
                float w0 = sWy[2 * n2], w1 = sWy[2 * n2 + 1];
                float r0 = fmaf(w0, bv.x - a.x, a.x);
                float r1 = fmaf(w1, bv.y - a.y, a.y);
                *(__half2*)(smem + OFF_BH + k * BHSTR + n2 * 4) = __floats2half2_rn(r0, r1);
            }
        }
        __syncthreads();

        // ---- compute: 2 K16 steps ----
        const uint32_t abase = sb + OFF_A + (c % 3) * ABUF;
        #pragma unroll
        for (int s = 0; s < 2; s++) {
            uint32_t af[4][4];
            #pragma unroll
            for (int mi = 0; mi < 4; mi++) {
                uint32_t addr = abase + (uint32_t)((s * 2 * GM + wm + mi * 16) * 16) + laneoff;
                ldsm_x4(addr, af[mi]);
            }
            uint32_t bf[4][2];
            #pragma unroll
            for (int nj = 0; nj < 4; nj++) {
                uint32_t addr = bh + (uint32_t)((16 * s + (lane & 15)) * BHSTR + (wn + nj * 8) * 2);
                ldsm_x2_trans(addr, bf[nj]);
            }
            #pragma unroll
            for (int mi = 0; mi < 4; mi++)
                #pragma unroll
                for (int nj = 0; nj < 4; nj++)
                    mma_f16(acc[mi][nj],
                            af[mi][0], af[mi][1], af[mi][2], af[mi][3],
                            bf[nj][0], bf[nj][1]);
        }
        if (c + 2 < NCH) prefetch(c + 2);
    }

    // ---- fused epilogue ----
    const float al = __ldg(&alpha[0]);
    #pragma unroll
    for (int mi = 0; mi < 4; mi++) {
        const int r0 = wm + mi * 16 + lg;
        const float w0a = __ldg(&w_ext[(size_t)r0 * 257]);
        const float bea = __ldg(&b_ext[r0]);
        const float w0b = __ldg(&w_ext[(size_t)(r0 + 8) * 257]);
        const float beb = __ldg(&b_ext[r0 + 8]);
        #pragma unroll
        for (int nj = 0; nj < 4; nj++) {
            const int cl  = wn + nj * 8 + 2 * lt;
            const int col = n0 + cl;
            const float s0 = sSm[cl], s1 = sSm[cl + 1];

            size_t oa = ((size_t)b * C + r0) * HW + col;
            size_t ob = oa + (size_t)8 * HW;

            float2 fa = *(const float2*)(f + oa);
            float2 fb = *(const float2*)(f + ob);
            float2 ra, rb;
            ra.x = fmaxf(fa.x + al * (acc[mi][nj][0] + w0a * s0 + bea), 0.f);
            ra.y = fmaxf(fa.y + al * (acc[mi][nj][1] + w0a * s1 + bea), 0.f);
            rb.x = fmaxf(fb.x + al * (acc[mi][nj][2] + w0b * s0 + beb), 0.f);
            rb.y = fmaxf(fb.y + al * (acc[mi][nj][3] + w0b * s1 + beb), 0.f);
            *(float2*)(out + oa) = ra;
            *(float2*)(out + ob) = rb;
        }
    }
}

// ---------------------------------------------------------------------------
extern "C" void kernel_launch(void* const* d_in, const int* in_sizes, int n_in,
                              void* d_out, int out_size)
{
    const float* features = (const float*)d_in[0];
    const float* P2       = (const float*)d_in[1];
    const float* w_disp   = (const float*)d_in[2];
    const float* b_disp   = (const float*)d_in[3];
    const float* w_ext    = (const float*)d_in[4];
    const float* b_ext    = (const float*)d_in[5];
    const float* alpha    = (const float*)d_in[6];
    float* out = (float*)d_out;

    cudaFuncSetAttribute(gemm_mma_kernel,
                         cudaFuncAttributeMaxDynamicSharedMemorySize, SMEM_TOT);

    prepA_kernel <<<C, C>>>(w_ext);
    convA_kernel <<<dim3(HW / 512, 4, Bz), 256>>>(features, w_disp);
    phaseB_kernel<<<dim3(HW / 256, Bz), 256>>>(P2, b_disp);
    gemm_mma_kernel<<<dim3(HW / GN, 1, Bz), 512, SMEM_TOT>>>(
        features, w_ext, b_ext, alpha, out);
}

// round 15
// speedup vs baseline: 1.9036x; 1.0626x over previous
#include <cuda_runtime.h>
#include <cuda_fp16.h>
#include <math.h>
#include <stdint.h>

#define Bz 16
#define C 256
#define H 48
#define W 160
#define HW (H*W)            // 7680
#define CHW (C*HW)          // 1966080

typedef unsigned long long ull;

// Scratch (__device__ globals; no allocations allowed)
__device__ float  g_G[(size_t)Bz * 4 * 9 * HW];
__device__ int    g_y0[Bz * HW];
__device__ float  g_wy[Bz * HW];
__device__ float  g_samp0[Bz * HW];
__device__ __half g_Ah[C * C];   // w_ext[:,1:] f16, blocked [k/8][m][8k]

// ===================== PTX helpers ==============================
__device__ __forceinline__ void fma2(ull& d, ull a, ull b) {
    asm("fma.rn.f32x2 %0, %1, %2, %0;" : "+l"(d) : "l"(a), "l"(b));
}
__device__ __forceinline__ ull pack2(float lo, float hi) {
    ull r; asm("mov.b64 %0, {%1, %2};" : "=l"(r) : "f"(lo), "f"(hi)); return r;
}
__device__ __forceinline__ uint32_t smem_u32(const void* p) {
    uint32_t a;
    asm("{ .reg .u64 t; cvta.to.shared.u64 t, %1; cvt.u32.u64 %0, t; }" : "=r"(a) : "l"(p));
    return a;
}
#define CP_ASYNC_4(dst, src) \
    asm volatile("cp.async.ca.shared.global [%0], [%1], 4;" :: "r"(dst), "l"(src))
#define CP_ASYNC_16(dst, src) \
    asm volatile("cp.async.cg.shared.global [%0], [%1], 16;" :: "r"(dst), "l"(src))
#define CP_COMMIT() asm volatile("cp.async.commit_group;" ::: "memory")
#define CP_WAIT(n)  asm volatile("cp.async.wait_group %0;" :: "n"(n) : "memory")

__device__ __forceinline__ void ldsm_x4(uint32_t addr, uint32_t* r) {
    asm volatile("ldmatrix.sync.aligned.m8n8.x4.shared.b16 {%0,%1,%2,%3}, [%4];"
        : "=r"(r[0]), "=r"(r[1]), "=r"(r[2]), "=r"(r[3]) : "r"(addr));
}
__device__ __forceinline__ void ldsm_x2_trans(uint32_t addr, uint32_t* r) {
    asm volatile("ldmatrix.sync.aligned.m8n8.x2.trans.shared.b16 {%0,%1}, [%2];"
        : "=r"(r[0]), "=r"(r[1]) : "r"(addr));
}

// m16n8k16 f16 MMA, f32 accumulate
__device__ __forceinline__ void mma_f16(float* d,
                                        uint32_t a0, uint32_t a1, uint32_t a2, uint32_t a3,
                                        uint32_t b0, uint32_t b1) {
    asm volatile(
        "mma.sync.aligned.m16n8k16.row.col.f32.f16.f16.f32 "
        "{%0,%1,%2,%3}, {%4,%5,%6,%7}, {%8,%9}, {%0,%1,%2,%3};"
        : "+f"(d[0]), "+f"(d[1]), "+f"(d[2]), "+f"(d[3])
        : "r"(a0), "r"(a1), "r"(a2), "r"(a3), "r"(b0), "r"(b1));
}

// ---------------------------------------------------------------------------
// Kernel 0: w_ext[:,1:] -> g_Ah blocked [k/8][m][8k], f16.
// ---------------------------------------------------------------------------
__global__ void prepA_kernel(const float* __restrict__ w_ext)
{
    const int m = blockIdx.x, k = threadIdx.x;
    g_Ah[(k >> 3) * (C * 8) + m * 8 + (k & 7)] =
        __float2half(__ldg(&w_ext[(size_t)m * 257 + 1 + k]));
}

// ---------------------------------------------------------------------------
// Kernel 1: conv phase A, 4 channel-chunks (960 blocks).
// ---------------------------------------------------------------------------
#define CCH 64
__global__ __launch_bounds__(256) void convA_kernel(const float* __restrict__ f,
                                                    const float* __restrict__ w_disp)
{
    __shared__ ull sW2[CCH * 9];
    const int tid   = threadIdx.x;
    const int chunk = blockIdx.y;
    const int b     = blockIdx.z;
    const int p2    = blockIdx.x * 512 + tid * 2;

    for (int i = tid; i < CCH * 9; i += 256) {
        float w = __ldg(&w_disp[chunk * CCH * 9 + i]);
        sW2[i] = pack2(w, w);
    }
    __syncthreads();

    const float* Fb = f + (size_t)b * CHW + (size_t)chunk * CCH * HW;
    ull acc[9];
    #pragma unroll
    for (int j = 0; j < 9; j++) acc[j] = 0ull;

    #pragma unroll 4
    for (int c = 0; c < CCH; c++) {
        ull v = *(const ull*)&Fb[(size_t)c * HW + p2];
        #pragma unroll
        for (int j = 0; j < 9; j++) fma2(acc[j], sW2[c * 9 + j], v);
    }
    #pragma unroll
    for (int j = 0; j < 9; j++)
        *(ull*)&g_G[((size_t)((b * 4 + chunk) * 9 + j)) * HW + p2] = acc[j];
}

// ---------------------------------------------------------------------------
// Kernel 2: 3x3 combine, tanh -> disp, sampling params.
// ---------------------------------------------------------------------------
__global__ __launch_bounds__(256) void phaseB_kernel(const float* __restrict__ P2,
                                                     const float* __restrict__ b_disp)
{
    const int b = blockIdx.y;
    const int p = blockIdx.x * 256 + threadIdx.x;
    const int y = p / W, x = p % W;

    float s = 0.f;
    #pragma unroll
    for (int dy = -1; dy <= 1; dy++) {
        int yy = y + dy;
        if (yy < 0 || yy >= H) continue;
        #pragma unroll
        for (int dx = -1; dx <= 1; dx++) {
            int xx = x + dx;
            if (xx < 0 || xx >= W) continue;
            int j = (dy + 1) * 3 + (dx + 1);
            #pragma unroll
            for (int ch = 0; ch < 4; ch++)
                s += g_G[((size_t)((b * 4 + ch) * 9 + j)) * HW + yy * W + xx];
        }
    }
    const float dval = 0.1f * tanhf(s + __ldg(&b_disp[0]));

    const float fyv = __ldg(&P2[b * 12 + 5]) * 0.0625f;
    const float cyv = __ldg(&P2[b * 12 + 6]) * 0.0625f;
    const float Tyv = __ldg(&P2[b * 12 + 7]) * 0.0625f;
    const float denom = fabsf(fyv * 1.65f + Tyv) + 1e-10f;

    const float yf    = (float)y;
    const float ysb   = fmaxf(1.535f * (yf - cyv) / (2.f * (1.65f - 0.5f * 1.535f)), 0.f) * (1.f / 24.f);
    const float ybase = -1.f + yf * (2.f / 47.f);
    const float gy    = ybase + ysb + dval;

    float iy  = fminf(fmaxf((gy + 1.f) * 0.5f * 47.f, 0.f), 47.f);
    float y0f = floorf(iy);
    float wy  = iy - y0f;
    int y0 = (int)y0f;
    int y1 = min(y0 + 1, H - 1);

    const float sc = fyv * 0.54f / denom;
    float d0 = fmaxf(sc * (y0f - cyv), 0.f);
    float d1 = fmaxf(sc * ((float)y1 - cyv), 0.f);

    const int gi = b * HW + p;
    g_y0[gi]    = y0;
    g_wy[gi]    = wy;
    g_samp0[gi] = d0 + wy * (d1 - d0);
}

// ---------------------------------------------------------------------------
// Kernel 3: f16 m16n8k16 mma.sync GEMM, 2 CTAs/SM.
// 256 threads (8 warps, 4m x 2n), GM=256, GN=64, K chunks of 32.
// cp.async fp32 taps (2-slot) -> staged f16 Bh (1 slot) -> ldmatrix.
// ---------------------------------------------------------------------------
#define GM 256
#define GN 64
#define GK 32
#define NCH (C / GK)                    // 8
#define BSTR 68                         // fp32 tap row pitch (floats)
#define BHSTR 144                       // f16 Bh row pitch (bytes): 64 + 8 pad halves
#define ABUF  (GM * GK * 2)             // 16384 B (f16 blocked)
#define VBUF  (GK * BSTR * 4)           // 8704 B
#define OFF_A   0
#define OFF_V0  (3 * ABUF)              // 49152
#define OFF_V1  (OFF_V0 + 2 * VBUF)     // 66560
#define OFF_BH  (OFF_V1 + 2 * VBUF)     // 83968
#define OFF_CTL (OFF_BH + GK * BHSTR)   // 88576
#define SMEM_TOT (OFF_CTL + 1280)       // 89856

__global__ __launch_bounds__(256, 2) void gemm_mma_kernel(
    const float* __restrict__ f,
    const float* __restrict__ w_ext,
    const float* __restrict__ b_ext,
    const float* __restrict__ alpha,
    float* __restrict__ out)
{
    extern __shared__ __align__(16) char smem[];
    const uint32_t sb = smem_u32(smem);

    int*   sO0 = (int*)  (smem + OFF_CTL);          // 64 ints
    int*   sO1 = (int*)  (smem + OFF_CTL + 256);
    float* sWy = (float*)(smem + OFF_CTL + 512);
    float* sSm = (float*)(smem + OFF_CTL + 768);

    const int tid  = threadIdx.x;
    const int warp = tid >> 5;
    const int lane = tid & 31;
    const int lg   = lane >> 2;
    const int lt   = lane & 3;
    const int wm   = (warp >> 1) * 64;     // 0,64,128,192
    const int wn   = (warp & 1) * 32;      // 0,32

    const int b  = blockIdx.z;
    const int n0 = blockIdx.x * GN;
    const float* Fb = f + (size_t)b * CHW;

    if (tid < GN) {
        int p   = n0 + tid;
        int y0v = g_y0[b * HW + p];
        int x   = p % W;
        sO0[tid] = y0v * W + x;
        sO1[tid] = min(y0v + 1, H - 1) * W + x;
        sWy[tid] = g_wy[b * HW + p];
        sSm[tid] = g_samp0[b * HW + p];
    }
    __syncthreads();

    // ---- async prefetch: A -> slot c%3, taps -> slot c&1 ----
    auto prefetch = [&](int c) {
        const uint32_t ab  = sb + OFF_A  + (c % 3) * ABUF;
        const uint32_t v0b = sb + OFF_V0 + (c & 1) * VBUF;
        const uint32_t v1b = sb + OFF_V1 + (c & 1) * VBUF;
        #pragma unroll
        for (int i = 0; i < 4; i++) {
            int e = tid + i * 256;            // 1024 16B units of A (f16 blocked)
            const __half* src = g_Ah + (size_t)(c * 4 + (e >> 8)) * (C * 8) + (e & 255) * 8;
            CP_ASYNC_16(ab + e * 16, src);
        }
        #pragma unroll
        for (int i = 0; i < 8; i++) {
            int e = tid + i * 256;            // 2048 tap positions
            int k = e >> 6;
            int n = e & 63;
            const float* fk = Fb + (size_t)(c * GK + k) * HW;
            uint32_t doff = (k * BSTR + n) * 4;
            CP_ASYNC_4(v0b + doff, fk + sO0[n]);
            CP_ASYNC_4(v1b + doff, fk + sO1[n]);
        }
        CP_COMMIT();
    };

    float acc[4][4][4];
    #pragma unroll
    for (int mi = 0; mi < 4; mi++)
        #pragma unroll
        for (int nj = 0; nj < 4; nj++)
            #pragma unroll
            for (int t = 0; t < 4; t++) acc[mi][nj][t] = 0.f;

    const uint32_t laneoff = (uint32_t)(((lane >> 4) * GM + (lane & 15)) * 16);
    const uint32_t bh = sb + OFF_BH;

    prefetch(0);
    prefetch(1);

    for (int c = 0; c < NCH; c++) {
        if (c < NCH - 1) CP_WAIT(1); else CP_WAIT(0);
        __syncthreads();

        // ---- stage: lerp fp32 taps -> f16 Bh[k][n] ----
        {
            const float* V0 = (const float*)(smem + OFF_V0 + (c & 1) * VBUF);
            const float* V1 = (const float*)(smem + OFF_V1 + (c & 1) * VBUF);
            #pragma unroll
            for (int i = 0; i < 4; i++) {
                int e2 = tid + i * 256;       // 1024 half2 positions
                int k  = e2 >> 5;
                int n2 = e2 & 31;
                int idx = k * BSTR + 2 * n2;
                float2 a = *(const float2*)(V0 + idx);
                float2 bv = *(const float2*)(V1 + idx);
                float w0 = sWy[2 * n2], w1 = sWy[2 * n2 + 1];
                float r0 = fmaf(w0, bv.x - a.x, a.x);
                float r1 = fmaf(w1, bv.y - a.y, a.y);
                *(__half2*)(smem + OFF_BH + k * BHSTR + n2 * 4) = __floats2half2_rn(r0, r1);
            }
        }
        __syncthreads();

        // ---- compute: 2 K16 steps ----
        const uint32_t abase = sb + OFF_A + (c % 3) * ABUF;
        #pragma unroll
        for (int s = 0; s < 2; s++) {
            uint32_t af[4][4];
            #pragma unroll
            for (int mi = 0; mi < 4; mi++) {
                uint32_t addr = abase + (uint32_t)((s * 2 * GM + wm + mi * 16) * 16) + laneoff;
                ldsm_x4(addr, af[mi]);
            }
            uint32_t bf[4][2];
            #pragma unroll
            for (int nj = 0; nj < 4; nj++) {
                uint32_t addr = bh + (uint32_t)((16 * s + (lane & 15)) * BHSTR + (wn + nj * 8) * 2);
                ldsm_x2_trans(addr, bf[nj]);
            }
            #pragma unroll
            for (int mi = 0; mi < 4; mi++)
                #pragma unroll
                for (int nj = 0; nj < 4; nj++)
                    mma_f16(acc[mi][nj],
                            af[mi][0], af[mi][1], af[mi][2], af[mi][3],
                            bf[nj][0], bf[nj][1]);
        }
        if (c + 2 < NCH) prefetch(c + 2);
    }

    // ---- fused epilogue ----
    const float al = __ldg(&alpha[0]);
    #pragma unroll
    for (int mi = 0; mi < 4; mi++) {
        const int r0 = wm + mi * 16 + lg;
        const float w0a = __ldg(&w_ext[(size_t)r0 * 257]);
        const float bea = __ldg(&b_ext[r0]);
        const float w0b = __ldg(&w_ext[(size_t)(r0 + 8) * 257]);
        const float beb = __ldg(&b_ext[r0 + 8]);
        #pragma unroll
        for (int nj = 0; nj < 4; nj++) {
            const int cl  = wn + nj * 8 + 2 * lt;
            const int col = n0 + cl;
            const float s0 = sSm[cl], s1 = sSm[cl + 1];

            size_t oa = ((size_t)b * C + r0) * HW + col;
            size_t ob = oa + (size_t)8 * HW;

            float2 fa = *(const float2*)(f + oa);
            float2 fb = *(const float2*)(f + ob);
            float2 ra, rb;
            ra.x = fmaxf(fa.x + al * (acc[mi][nj][0] + w0a * s0 + bea), 0.f);
            ra.y = fmaxf(fa.y + al * (acc[mi][nj][1] + w0a * s1 + bea), 0.f);
            rb.x = fmaxf(fb.x + al * (acc[mi][nj][2] + w0b * s0 + beb), 0.f);
            rb.y = fmaxf(fb.y + al * (acc[mi][nj][3] + w0b * s1 + beb), 0.f);
            *(float2*)(out + oa) = ra;
            *(float2*)(out + ob) = rb;
        }
    }
}

// ---------------------------------------------------------------------------
extern "C" void kernel_launch(void* const* d_in, const int* in_sizes, int n_in,
                              void* d_out, int out_size)
{
    const float* features = (const float*)d_in[0];
    const float* P2       = (const float*)d_in[1];
    const float* w_disp   = (const float*)d_in[2];
    const float* b_disp   = (const float*)d_in[3];
    const float* w_ext    = (const float*)d_in[4];
    const float* b_ext    = (const float*)d_in[5];
    const float* alpha    = (const float*)d_in[6];
    float* out = (float*)d_out;

    cudaFuncSetAttribute(gemm_mma_kernel,
                         cudaFuncAttributeMaxDynamicSharedMemorySize, SMEM_TOT);

    prepA_kernel <<<C, C>>>(w_ext);
    convA_kernel <<<dim3(HW / 512, 4, Bz), 256>>>(features, w_disp);
    phaseB_kernel<<<dim3(HW / 256, Bz), 256>>>(P2, b_disp);
    gemm_mma_kernel<<<dim3(HW / GN, 1, Bz), 256, SMEM_TOT>>>(
        features, w_ext, b_ext, alpha, out);
}